// round 3
// baseline (speedup 1.0000x reference)
#include <cuda_runtime.h>
#include <math.h>

#define NPT   512
#define LANG  500
#define AA    32
#define KK    64
#define NPAIR (LANG*AA)
#define LOG2PI_F     1.8378770664093453f
#define HALF3LOG2PI  (1.5f*LOG2PI_F)

// ---------------- device scratch (no allocations allowed) ----------------
__device__ float g_M[NPT*NPT];        // L + I, Cholesky-factored in place (off-diag panels)
__device__ float g_diag[NPT];         // pivots d_k of the big factorization
__device__ float g_q[NPT];
__device__ float g_chr[LANG*KK*3];
__device__ float g_pair[NPAIR];       // logdet(sub) + step4 per (lang, a)
__device__ float g_w2inv[9];
__device__ float g_w1inv[9];
__device__ float g_step2;

// ---------------- helpers ----------------
__device__ __forceinline__ void inv3(const float* w, float* o){
    float a=w[0],b=w[1],c=w[2],d=w[3],e=w[4],f=w[5],g=w[6],h=w[7],i=w[8];
    float det = a*(e*i-f*h) - b*(d*i-f*g) + c*(d*h-e*g);
    float id  = 1.0f/det;
    o[0]=(e*i-f*h)*id; o[1]=(c*h-b*i)*id; o[2]=(b*f-c*e)*id;
    o[3]=(f*g-d*i)*id; o[4]=(a*i-c*g)*id; o[5]=(c*d-a*f)*id;
    o[6]=(d*h-e*g)*id; o[7]=(b*g-a*h)*id; o[8]=(a*e-b*d)*id;
}

// ---------------- K1: q vector, step2, 3x3 inverses ----------------
__global__ void k_prep(const float* __restrict__ mus,
                       const float* __restrict__ fw1, const float* __restrict__ fb1,
                       const float* __restrict__ fw2, const float* __restrict__ fb2,
                       const float* __restrict__ dw1, const float* __restrict__ dw2){
    int t = threadIdx.x;                       // 512 threads
    __shared__ float red[512];
    float contrib = 0.f;
    if (t < NPT){
        float m0=mus[t*3+0], m1=mus[t*3+1], m2=mus[t*3+2];
        float h0 = tanhf(fw1[0]*m0+fw1[1]*m1+fw1[2]*m2+fb1[0]);
        float h1 = tanhf(fw1[3]*m0+fw1[4]*m1+fw1[5]*m2+fb1[1]);
        float h2 = tanhf(fw1[6]*m0+fw1[7]*m1+fw1[8]*m2+fb1[2]);
        float lq = fw2[0]*h0+fw2[1]*h1+fw2[2]*h2+fb2[0];
        g_q[t] = expf(lq);
        contrib = -0.5f*(m0*m0+m1*m1+m2*m2) - HALF3LOG2PI;
    }
    red[t]=contrib; __syncthreads();
    for (int s=256;s>0;s>>=1){ if(t<s) red[t]+=red[t+s]; __syncthreads(); }
    if (t==0){
        g_step2 = red[0];
        inv3(dw1, g_w1inv);
        inv3(dw2, g_w2inv);
    }
}

// ---------------- K2: chromes via inverse flow ----------------
__global__ void k_chromes(const float* __restrict__ colors,
                          const float* __restrict__ db1, const float* __restrict__ db2){
    int idx = blockIdx.x*blockDim.x + threadIdx.x;   // 0 .. 31999
    if (idx >= LANG*KK) return;
    float c0 = colors[idx*3+0]-db2[0];
    float c1 = colors[idx*3+1]-db2[1];
    float c2 = colors[idx*3+2]-db2[2];
    float z0 = g_w2inv[0]*c0 + g_w2inv[1]*c1 + g_w2inv[2]*c2;
    float z1 = g_w2inv[3]*c0 + g_w2inv[4]*c1 + g_w2inv[5]*c2;
    float z2 = g_w2inv[6]*c0 + g_w2inv[7]*c1 + g_w2inv[8]*c2;
    const float lim = 1.0f - 1e-6f;
    z0 = atanhf(fminf(fmaxf(z0,-lim),lim));
    z1 = atanhf(fminf(fmaxf(z1,-lim),lim));
    z2 = atanhf(fminf(fmaxf(z2,-lim),lim));
    float y0 = z0 - db1[0], y1 = z1 - db1[1], y2 = z2 - db1[2];
    g_chr[idx*3+0] = g_w1inv[0]*y0 + g_w1inv[1]*y1 + g_w1inv[2]*y2;
    g_chr[idx*3+1] = g_w1inv[3]*y0 + g_w1inv[4]*y1 + g_w1inv[5]*y2;
    g_chr[idx*3+2] = g_w1inv[6]*y0 + g_w1inv[7]*y1 + g_w1inv[8]*y2;
}

// ---------------- K3: build M = L + I (512 x 512) ----------------
__global__ void k_buildM(const float* __restrict__ mus){
    int i = blockIdx.x, j = threadIdx.x;
    float dx = mus[i*3+0]-mus[j*3+0];
    float dy = mus[i*3+1]-mus[j*3+1];
    float dz = mus[i*3+2]-mus[j*3+2];
    float v = g_q[i]*g_q[j]*expf(-0.5f*(dx*dx+dy*dy+dz*dz));
    if (i==j) v += 1.0f;
    g_M[i*NPT+j] = v;
}

// ---------------- K4: 16000 x (64x64 LDL^T logdet + step4) ----------------
__global__ __launch_bounds__(64) void k_pairs(const int* __restrict__ align,
                                              const float* __restrict__ mus){
    int pid = blockIdx.x;
    int t   = threadIdx.x;                      // 64 threads, thread t owns row t
    __shared__ float smx[64], smy[64], smz[64], sq[64], sCol[64], sred[64];
    int lang = pid >> 5;
    int idx  = align[pid*64 + t];
    float mx = mus[idx*3+0], my = mus[idx*3+1], mz = mus[idx*3+2];
    float qv = g_q[idx];
    smx[t]=mx; smy[t]=my; smz[t]=mz; sq[t]=qv;
    // step4 contribution for k = t
    const float* ch = g_chr + (lang*KK + t)*3;
    float dx = ch[0]-mx, dy = ch[1]-my, dz = ch[2]-mz;
    float acc = -0.5f*(dx*dx+dy*dy+dz*dz) - HALF3LOG2PI;
    __syncthreads();

    // build row t of sub (lower triangle only), register-resident
    float a[64];
    const int wmax = t | 31;                    // warp-uniform row bound
    if (wmax == 63){
        #pragma unroll
        for (int j=0;j<64;j++){
            if (j < t){
                float ex=mx-smx[j], ey=my-smy[j], ez=mz-smz[j];
                a[j] = qv*sq[j]*expf(-0.5f*(ex*ex+ey*ey+ez*ez));
            } else if (j == t){
                a[j] = qv*qv + 1e-6f;
            }
        }
    } else {
        #pragma unroll
        for (int j=0;j<32;j++){
            if (j < t){
                float ex=mx-smx[j], ey=my-smy[j], ez=mz-smz[j];
                a[j] = qv*sq[j]*expf(-0.5f*(ex*ex+ey*ey+ez*ez));
            } else if (j == t){
                a[j] = qv*qv + 1e-6f;
            }
        }
    }

    // LDL^T: logdet = sum log(pivots); 2 bar.sync per column
    float mypiv = 1.0f;
    #pragma unroll
    for (int k=0;k<64;k++){
        if (t >= k) sCol[t] = a[k];
        __syncthreads();
        float piv = fmaxf(sCol[k], 1e-7f);      // true pivots >= jitter 1e-6
        if (t == k) mypiv = piv;
        float f = __fdividef(a[k], piv);
        if (wmax == 63){
            #pragma unroll
            for (int j=k+1;j<64;j++) if (j<=t) a[j] -= f*sCol[j];
        } else if (k < 31){
            #pragma unroll
            for (int j=k+1;j<32;j++) if (j<=t) a[j] -= f*sCol[j];
        }
        __syncthreads();
    }
    acc += logf(mypiv);                         // each thread adds its own pivot's log

    sred[t] = acc; __syncthreads();
    #pragma unroll
    for (int s=32;s>0;s>>=1){ if (t<s) sred[t]+=sred[t+s]; __syncthreads(); }
    if (t==0) g_pair[pid] = sred[0];
}

// ---------------- K5a: panel (redundant diag factor + TRSM), NB = 64 ----------------
__global__ __launch_bounds__(64) void chol_panel(int p){
    int t = threadIdx.x;
    __shared__ float sL[64][65];
    __shared__ float sCol[64];
    __shared__ float sPiv[64];
    __shared__ float sID[64];
    float a[64];
    float* Mrow = g_M + (p*64 + t)*NPT + p*64;  // diag block rows
    #pragma unroll
    for (int j=0;j<64;j++) a[j] = Mrow[j];
    const int wmax = t | 31;
    #pragma unroll
    for (int k=0;k<64;k++){
        if (t >= k) sCol[t] = a[k];
        __syncthreads();
        float piv = fmaxf(sCol[k], 1e-30f);
        if (t == k) sPiv[k] = piv;
        float f = __fdividef(a[k], piv);
        if (wmax == 63){
            #pragma unroll
            for (int j=k+1;j<64;j++) if (j<=t) a[j] -= f*sCol[j];
        } else if (k < 31){
            #pragma unroll
            for (int j=k+1;j<32;j++) if (j<=t) a[j] -= f*sCol[j];
        }
        __syncthreads();
    }
    sID[t] = rsqrtf(sPiv[t]);                  // 1 / l_jj
    __syncthreads();
    // true Cholesky L11 into shared: L[t][j] = a[j] * rsqrt(d_j)
    #pragma unroll
    for (int j=0;j<64;j++) if (j<=t) sL[t][j] = a[j]*sID[j];
    __syncthreads();

    if (blockIdx.x == 0){
        g_diag[p*64 + t] = sPiv[t];            // pivots only; g_M diag untouched (no race)
    } else {
        int rb = p + blockIdx.x;
        float* Brow = g_M + (rb*64 + t)*NPT + p*64;
        float b[64];
        #pragma unroll
        for (int j=0;j<64;j++) b[j] = Brow[j];
        #pragma unroll
        for (int j=0;j<64;j++){
            float s0=0.f,s1=0.f,s2=0.f,s3=0.f;
            int m=0;
            #pragma unroll
            for (; m+3<j; m+=4){
                s0 += b[m+0]*sL[j][m+0];
                s1 += b[m+1]*sL[j][m+1];
                s2 += b[m+2]*sL[j][m+2];
                s3 += b[m+3]*sL[j][m+3];
            }
            #pragma unroll
            for (; m<j; m++) s0 += b[m]*sL[j][m];
            b[j] = (b[j] - ((s0+s1)+(s2+s3))) * sID[j];
        }
        #pragma unroll
        for (int j=0;j<64;j++) Brow[j] = b[j];
    }
}

// ---------------- K5b: trailing SYRK update, 64x64 tiles ----------------
__global__ __launch_bounds__(256) void chol_syrk(int p){
    int t = threadIdx.x;
    int tid = blockIdx.x;
    int br = 0;
    while ((br+1)*(br+2)/2 <= tid) br++;
    int bc = tid - br*(br+1)/2;
    int bi = p+1+br, bj = p+1+bc;
    __shared__ float sA[64][65], sB[64][65];
    const float* A = g_M + (bi*64)*NPT + p*64;
    const float* B = g_M + (bj*64)*NPT + p*64;
    for (int e=t; e<4096; e+=256){
        int i=e>>6, j=e&63;
        sA[i][j] = A[i*NPT+j];
        sB[i][j] = B[i*NPT+j];
    }
    __syncthreads();
    int ty = t>>4, tx = t&15;
    int i0 = ty*4, j0 = tx*4;
    float acc[4][4];
    #pragma unroll
    for (int ii=0;ii<4;ii++)
        #pragma unroll
        for (int jj=0;jj<4;jj++) acc[ii][jj]=0.f;
    #pragma unroll
    for (int k=0;k<64;k++){
        float av[4], bv[4];
        #pragma unroll
        for (int ii=0;ii<4;ii++) av[ii]=sA[i0+ii][k];
        #pragma unroll
        for (int jj=0;jj<4;jj++) bv[jj]=sB[j0+jj][k];
        #pragma unroll
        for (int ii=0;ii<4;ii++)
            #pragma unroll
            for (int jj=0;jj<4;jj++) acc[ii][jj] += av[ii]*bv[jj];
    }
    float* C = g_M + (bi*64)*NPT + bj*64;
    #pragma unroll
    for (int ii=0;ii<4;ii++)
        #pragma unroll
        for (int jj=0;jj<4;jj++)
            C[(i0+ii)*NPT + (j0+jj)] -= acc[ii][jj];
}

// ---------------- K6: logsumexp + final assembly ----------------
__global__ void k_final(float* __restrict__ out){
    int t = threadIdx.x;                        // 512 threads
    __shared__ float red[512];
    __shared__ float s_sumlse;
    float lse = 0.f;
    if (t < LANG){
        const float* v = g_pair + t*AA;
        float mx = -3.4e38f;
        #pragma unroll
        for (int a=0;a<AA;a++) mx = fmaxf(mx, v[a]);
        float s = 0.f;
        #pragma unroll
        for (int a=0;a<AA;a++) s += expf(v[a]-mx);
        lse = mx + logf(s);
    }
    red[t]=lse; __syncthreads();
    for (int s=256;s>0;s>>=1){ if(t<s) red[t]+=red[t+s]; __syncthreads(); }
    if (t==0) s_sumlse = red[0];
    __syncthreads();
    // logdet(L+I) = sum log(pivots)
    float ld = logf(g_diag[t]);
    red[t]=ld; __syncthreads();
    for (int s=256;s>0;s>>=1){ if(t<s) red[t]+=red[t+s]; __syncthreads(); }
    if (t==0){
        float logdetLI = red[0];
        float step1 = 512.f*logf(500.f) - 500.f - lgammaf(513.f);
        out[0] = -(step1 + g_step2 + s_sumlse - (float)LANG*logdetLI);
    }
}

// ---------------- launch ----------------
extern "C" void kernel_launch(void* const* d_in, const int* in_sizes, int n_in,
                              void* d_out, int out_size){
    const float* colors = (const float*)d_in[0];
    const int*   align  = (const int*)  d_in[1];
    const float* mus    = (const float*)d_in[2];
    const float* fw1    = (const float*)d_in[3];
    const float* fb1    = (const float*)d_in[4];
    const float* fw2    = (const float*)d_in[5];
    const float* fb2    = (const float*)d_in[6];
    const float* dw1    = (const float*)d_in[7];
    const float* db1    = (const float*)d_in[8];
    const float* dw2    = (const float*)d_in[9];
    const float* db2    = (const float*)d_in[10];

    k_prep<<<1, 512>>>(mus, fw1, fb1, fw2, fb2, dw1, dw2);
    k_chromes<<<(LANG*KK + 255)/256, 256>>>(colors, db1, db2);
    k_buildM<<<NPT, NPT>>>(mus);
    k_pairs<<<NPAIR, 64>>>(align, mus);
    for (int p=0; p<8; p++){
        chol_panel<<<8-p, 64>>>(p);
        int m = 7 - p;
        if (m > 0) chol_syrk<<<m*(m+1)/2, 256>>>(p);
    }
    k_final<<<1, 512>>>((float*)d_out);
}

// round 4
// speedup vs baseline: 1.6044x; 1.6044x over previous
#include <cuda_runtime.h>
#include <math.h>

#define NPT   512
#define LANG  500
#define AA    32
#define KK    64
#define NPAIR (LANG*AA)
#define CB    28
#define LOG2PI_F     1.8378770664093453f
#define HALF3LOG2PI  (1.5f*LOG2PI_F)

typedef unsigned long long ull;

// ---------------- device scratch (no allocations allowed) ----------------
__device__ float g_M[NPT*NPT];        // L + I, factored in place (off-diag panels)
__device__ float g_diag[NPT];         // pivots d_k of the big factorization
__device__ float g_q[NPT];
__device__ float g_chr[LANG*KK*3];
__device__ float g_pair[NPAIR];       // logdet(sub) + step4 per (lang, a)
__device__ float g_w2inv[9];
__device__ float g_w1inv[9];
__device__ float g_step2;
__device__ int   g_bar;               // persistent-kernel barrier counter

// ---------------- packed f32x2 helpers ----------------
__device__ __forceinline__ ull pack2(float lo, float hi){
    ull r; asm("mov.b64 %0, {%1, %2};" : "=l"(r) : "f"(lo), "f"(hi)); return r;
}
__device__ __forceinline__ void unpack2(ull v, float& lo, float& hi){
    asm("mov.b64 {%0, %1}, %2;" : "=f"(lo), "=f"(hi) : "l"(v));
}
__device__ __forceinline__ void ffma2(ull& d, ull a, ull b){
    asm("fma.rn.f32x2 %0, %1, %2, %0;" : "+l"(d) : "l"(a), "l"(b));
}
__device__ __forceinline__ float frcp(float x){
    float r; asm("rcp.approx.f32 %0, %1;" : "=f"(r) : "f"(x)); return r;
}

// ---------------- helpers ----------------
__device__ __forceinline__ void inv3(const float* w, float* o){
    float a=w[0],b=w[1],c=w[2],d=w[3],e=w[4],f=w[5],g=w[6],h=w[7],i=w[8];
    float det = a*(e*i-f*h) - b*(d*i-f*g) + c*(d*h-e*g);
    float id  = 1.0f/det;
    o[0]=(e*i-f*h)*id; o[1]=(c*h-b*i)*id; o[2]=(b*f-c*e)*id;
    o[3]=(f*g-d*i)*id; o[4]=(a*i-c*g)*id; o[5]=(c*d-a*f)*id;
    o[6]=(d*h-e*g)*id; o[7]=(b*g-a*h)*id; o[8]=(a*e-b*d)*id;
}

// ---------------- K1: q vector, step2, 3x3 inverses ----------------
__global__ void k_prep(const float* __restrict__ mus,
                       const float* __restrict__ fw1, const float* __restrict__ fb1,
                       const float* __restrict__ fw2, const float* __restrict__ fb2,
                       const float* __restrict__ dw1, const float* __restrict__ dw2){
    int t = threadIdx.x;                       // 512 threads
    __shared__ float red[512];
    float contrib = 0.f;
    if (t < NPT){
        float m0=mus[t*3+0], m1=mus[t*3+1], m2=mus[t*3+2];
        float h0 = tanhf(fw1[0]*m0+fw1[1]*m1+fw1[2]*m2+fb1[0]);
        float h1 = tanhf(fw1[3]*m0+fw1[4]*m1+fw1[5]*m2+fb1[1]);
        float h2 = tanhf(fw1[6]*m0+fw1[7]*m1+fw1[8]*m2+fb1[2]);
        float lq = fw2[0]*h0+fw2[1]*h1+fw2[2]*h2+fb2[0];
        g_q[t] = expf(lq);
        contrib = -0.5f*(m0*m0+m1*m1+m2*m2) - HALF3LOG2PI;
    }
    red[t]=contrib; __syncthreads();
    for (int s=256;s>0;s>>=1){ if(t<s) red[t]+=red[t+s]; __syncthreads(); }
    if (t==0){
        g_step2 = red[0];
        inv3(dw1, g_w1inv);
        inv3(dw2, g_w2inv);
    }
}

// ---------------- K2: chromes via inverse flow ----------------
__global__ void k_chromes(const float* __restrict__ colors,
                          const float* __restrict__ db1, const float* __restrict__ db2){
    int idx = blockIdx.x*blockDim.x + threadIdx.x;   // 0 .. 31999
    if (idx >= LANG*KK) return;
    float c0 = colors[idx*3+0]-db2[0];
    float c1 = colors[idx*3+1]-db2[1];
    float c2 = colors[idx*3+2]-db2[2];
    float z0 = g_w2inv[0]*c0 + g_w2inv[1]*c1 + g_w2inv[2]*c2;
    float z1 = g_w2inv[3]*c0 + g_w2inv[4]*c1 + g_w2inv[5]*c2;
    float z2 = g_w2inv[6]*c0 + g_w2inv[7]*c1 + g_w2inv[8]*c2;
    const float lim = 1.0f - 1e-6f;
    z0 = atanhf(fminf(fmaxf(z0,-lim),lim));
    z1 = atanhf(fminf(fmaxf(z1,-lim),lim));
    z2 = atanhf(fminf(fmaxf(z2,-lim),lim));
    float y0 = z0 - db1[0], y1 = z1 - db1[1], y2 = z2 - db1[2];
    g_chr[idx*3+0] = g_w1inv[0]*y0 + g_w1inv[1]*y1 + g_w1inv[2]*y2;
    g_chr[idx*3+1] = g_w1inv[3]*y0 + g_w1inv[4]*y1 + g_w1inv[5]*y2;
    g_chr[idx*3+2] = g_w1inv[6]*y0 + g_w1inv[7]*y1 + g_w1inv[8]*y2;
}

// ---------------- K3: build M = L + I (512 x 512); also reset barrier ----------------
__global__ void k_buildM(const float* __restrict__ mus){
    int i = blockIdx.x, j = threadIdx.x;
    if (i==0 && j==0) g_bar = 0;
    float dx = mus[i*3+0]-mus[j*3+0];
    float dy = mus[i*3+1]-mus[j*3+1];
    float dz = mus[i*3+2]-mus[j*3+2];
    float v = g_q[i]*g_q[j]*__expf(-0.5f*(dx*dx+dy*dy+dz*dz));
    if (i==j) v += 1.0f;
    g_M[i*NPT+j] = v;
}

// ---------------- K4: warp-per-pair 64x64 LDL^T logdet + step4 ----------------
// Lane l owns rows l (packed pairs PT[16]) and 63-l (PR[32]).
// Updates run unconditionally over full pair ranges; slots past a row's end
// hold garbage that is provably never read (rows are read as column sources
// only at steps <= their own index).
__device__ __forceinline__ float subent(float mx,float my,float mz,float q,
                                        float ox,float oy,float oz,float oq,
                                        int j,int row){
    float dx=mx-ox, dy=my-oy, dz=mz-oz;
    float d2 = dx*dx + dy*dy + dz*dz;
    float v = q*oq*__expf(-0.5f*d2);
    v = (j < row) ? v : 0.f;
    v = (j == row) ? (q*q + 1e-6f) : v;
    return v;
}

__global__ __launch_bounds__(128) void k_pairs2(const int* __restrict__ align,
                                                const float* __restrict__ mus){
    __shared__ float sx[4][64], sy[4][64], sz[4][64], sq[4][64];
    __shared__ __align__(16) float scol[4][2][64];

    int w   = threadIdx.x >> 5;
    int l   = threadIdx.x & 31;
    int pid = blockIdx.x*4 + w;
    int lang = pid >> 5;
    int rrow = 63 - l;

    // ---- stage mus/q for the 64 gathered points (lane l loads slots l, l+32)
    int base = pid*64;
    int i0 = align[base + l];
    int i1 = align[base + 32 + l];
    float t_x = mus[i0*3+0], t_y = mus[i0*3+1], t_z = mus[i0*3+2];
    float b_x = mus[i1*3+0], b_y = mus[i1*3+1], b_z = mus[i1*3+2];
    float qt  = g_q[i0];
    float q1  = g_q[i1];
    sx[w][l]=t_x;    sy[w][l]=t_y;    sz[w][l]=t_z;    sq[w][l]=qt;
    sx[w][32+l]=b_x; sy[w][32+l]=b_y; sz[w][32+l]=b_z; sq[w][32+l]=q1;

    // ---- step4 contributions for k = l and k = l+32
    const float* ch0 = g_chr + (lang*KK + l)*3;
    const float* ch1 = g_chr + (lang*KK + 32 + l)*3;
    float dx0=ch0[0]-t_x, dy0=ch0[1]-t_y, dz0=ch0[2]-t_z;
    float dx1=ch1[0]-b_x, dy1=ch1[1]-b_y, dz1=ch1[2]-b_z;
    float acc = -0.5f*(dx0*dx0+dy0*dy0+dz0*dz0) - HALF3LOG2PI
                -0.5f*(dx1*dx1+dy1*dy1+dz1*dz1) - HALF3LOG2PI;
    __syncwarp();

    // ---- row-r point data
    float r_x = sx[w][rrow], r_y = sy[w][rrow], r_z = sz[w][rrow], qr = sq[w][rrow];

    // ---- build packed rows
    ull PT[16];
    ull PR[32];
    #pragma unroll
    for (int j2=0;j2<32;j2++){
        int ja = 2*j2, jb = 2*j2+1;
        float ax=sx[w][ja], ay=sy[w][ja], az=sz[w][ja], aq=sq[w][ja];
        float bx=sx[w][jb], by=sy[w][jb], bz=sz[w][jb], bq=sq[w][jb];
        float eR0 = subent(r_x,r_y,r_z,qr, ax,ay,az,aq, ja, rrow);
        float eR1 = subent(r_x,r_y,r_z,qr, bx,by,bz,bq, jb, rrow);
        PR[j2] = pack2(eR0, eR1);
        if (j2 < 16){
            float eT0 = subent(t_x,t_y,t_z,qt, ax,ay,az,aq, ja, l);
            float eT1 = subent(t_x,t_y,t_z,qt, bx,by,bz,bq, jb, l);
            PT[j2] = pack2(eT0, eT1);
        }
    }

    // ---- LDL^T, one __syncwarp per column, double-buffered column
    float pT = 1.f, pR = 1.f;
    #pragma unroll
    for (int k=0;k<64;k++){
        float* sc = &scol[w][k & 1][0];
        float cT = 0.f;
        if (k < 32){
            float lo, hi; unpack2(PT[k>>1], lo, hi);
            cT = (k & 1) ? hi : lo;
        }
        float rlo, rhi; unpack2(PR[k>>1], rlo, rhi);
        float cR = (k & 1) ? rhi : rlo;
        if (k < 32 && l >= k) sc[l] = cT;
        if (rrow >= k)        sc[rrow] = cR;
        __syncwarp();
        float piv = fmaxf(sc[k], 1e-7f);      // true pivots >= jitter 1e-6
        pT = (k == l)    ? piv : pT;
        pR = (k == rrow) ? piv : pR;
        float rv = frcp(piv);
        float fT = cT*rv, fR = cR*rv;
        ull nT = pack2(-fT, -fT);
        ull nR = pack2(-fR, -fR);
        const ull* cp = (const ull*)sc;
        #pragma unroll
        for (int j2=0;j2<32;j2++){
            if (j2 >= ((k+1)>>1)){
                ull c = cp[j2];
                if (j2 < 16) ffma2(PT[j2], nT, c);
                ffma2(PR[j2], nR, c);
            }
        }
    }
    acc += logf(pT) + logf(pR);

    // ---- warp reduction
    #pragma unroll
    for (int o=16;o>0;o>>=1) acc += __shfl_down_sync(0xffffffffu, acc, o);
    if (l == 0) g_pair[pid] = acc;
}

// ---------------- K5: persistent 512x512 Cholesky (one launch) ----------------
__device__ __forceinline__ void gbar(int tgt){
    __syncthreads();
    if (threadIdx.x == 0){
        __threadfence();
        atomicAdd(&g_bar, 1);
        while (*((volatile int*)&g_bar) < tgt*CB) { __nanosleep(64); }
    }
    __syncthreads();
}

__global__ __launch_bounds__(256) void chol_all(){
    int b = blockIdx.x, t = threadIdx.x;
    __shared__ float sA[64][65];
    __shared__ float sB[64][65];
    __shared__ float sCol[64], sPiv[64], sID[64];
    int nbar = 0;
    #pragma unroll 1
    for (int p=0;p<8;p++){
        int m = 7-p;
        if (b <= m){
            // redundant diag-block LDL (thread t = row t, t<64)
            float a[64];
            if (t < 64){
                const float* Mrow = g_M + (p*64+t)*NPT + p*64;
                #pragma unroll
                for (int j=0;j<64;j++) a[j] = __ldcg(Mrow+j);
            }
            const int wmax = t | 31;
            #pragma unroll
            for (int k=0;k<64;k++){
                if (t < 64 && t >= k) sCol[t] = a[k];
                __syncthreads();
                if (t < 64){
                    float piv = fmaxf(sCol[k], 1e-30f);
                    if (t == k) sPiv[k] = piv;
                    float f = __fdividef(a[k], piv);
                    if (wmax == 63){
                        #pragma unroll
                        for (int j=k+1;j<64;j++) if (j<=t) a[j] -= f*sCol[j];
                    } else if (wmax == 31 && k < 31){
                        #pragma unroll
                        for (int j=k+1;j<32;j++) if (j<=t) a[j] -= f*sCol[j];
                    }
                }
                __syncthreads();
            }
            if (t < 64) sID[t] = rsqrtf(sPiv[t]);
            __syncthreads();
            if (t < 64){
                #pragma unroll
                for (int j=0;j<64;j++) if (j<=t) sA[t][j] = a[j]*sID[j];
            }
            __syncthreads();
            if (b == 0){
                if (t < 64) g_diag[p*64+t] = sPiv[t];
            } else if (t < 64){
                // TRSM for row-panel p+b
                float* Brow = g_M + ((p+b)*64+t)*NPT + p*64;
                float v[64];
                #pragma unroll
                for (int j=0;j<64;j++) v[j] = __ldcg(Brow+j);
                #pragma unroll
                for (int j=0;j<64;j++){
                    float s0=0.f,s1=0.f,s2=0.f,s3=0.f;
                    int q2=0;
                    #pragma unroll
                    for (; q2+3<j; q2+=4){
                        s0 += v[q2+0]*sA[j][q2+0];
                        s1 += v[q2+1]*sA[j][q2+1];
                        s2 += v[q2+2]*sA[j][q2+2];
                        s3 += v[q2+3]*sA[j][q2+3];
                    }
                    #pragma unroll
                    for (; q2<j; q2++) s0 += v[q2]*sA[j][q2];
                    v[j] = (v[j] - ((s0+s1)+(s2+s3))) * sID[j];
                }
                #pragma unroll
                for (int j=0;j<64;j++) Brow[j] = v[j];
            }
        }
        nbar++; gbar(nbar);

        int ntile = m*(m+1)/2;
        if (b < ntile){
            int br = 0;
            while ((br+1)*(br+2)/2 <= b) br++;
            int bc = b - br*(br+1)/2;
            int bi = p+1+br, bj = p+1+bc;
            const float* A = g_M + (bi*64)*NPT + p*64;
            const float* B = g_M + (bj*64)*NPT + p*64;
            for (int e=t; e<4096; e+=256){
                int i=e>>6, j=e&63;
                sA[i][j] = __ldcg(A + i*NPT + j);
                sB[i][j] = __ldcg(B + i*NPT + j);
            }
            __syncthreads();
            int ty=t>>4, tx=t&15, i0=ty*4, j0=tx*4;
            float acc[4][4];
            #pragma unroll
            for (int ii=0;ii<4;ii++)
                #pragma unroll
                for (int jj=0;jj<4;jj++) acc[ii][jj]=0.f;
            #pragma unroll
            for (int k=0;k<64;k++){
                float av[4], bv[4];
                #pragma unroll
                for (int ii=0;ii<4;ii++) av[ii]=sA[i0+ii][k];
                #pragma unroll
                for (int jj=0;jj<4;jj++) bv[jj]=sB[j0+jj][k];
                #pragma unroll
                for (int ii=0;ii<4;ii++)
                    #pragma unroll
                    for (int jj=0;jj<4;jj++) acc[ii][jj] += av[ii]*bv[jj];
            }
            float* C = g_M + (bi*64)*NPT + bj*64;
            #pragma unroll
            for (int ii=0;ii<4;ii++)
                #pragma unroll
                for (int jj=0;jj<4;jj++){
                    float* cp = C + (i0+ii)*NPT + (j0+jj);
                    *cp = __ldcg(cp) - acc[ii][jj];
                }
        }
        nbar++; gbar(nbar);
    }
}

// ---------------- K6: logsumexp + final assembly ----------------
__global__ void k_final(float* __restrict__ out){
    int t = threadIdx.x;                        // 512 threads
    __shared__ float red[512];
    __shared__ float s_sumlse;
    float lse = 0.f;
    if (t < LANG){
        const float* v = g_pair + t*AA;
        float mx = -3.4e38f;
        #pragma unroll
        for (int a=0;a<AA;a++) mx = fmaxf(mx, v[a]);
        float s = 0.f;
        #pragma unroll
        for (int a=0;a<AA;a++) s += expf(v[a]-mx);
        lse = mx + logf(s);
    }
    red[t]=lse; __syncthreads();
    for (int s=256;s>0;s>>=1){ if(t<s) red[t]+=red[t+s]; __syncthreads(); }
    if (t==0) s_sumlse = red[0];
    __syncthreads();
    float ld = logf(g_diag[t]);
    red[t]=ld; __syncthreads();
    for (int s=256;s>0;s>>=1){ if(t<s) red[t]+=red[t+s]; __syncthreads(); }
    if (t==0){
        float logdetLI = red[0];
        float step1 = 512.f*logf(500.f) - 500.f - lgammaf(513.f);
        out[0] = -(step1 + g_step2 + s_sumlse - (float)LANG*logdetLI);
    }
}

// ---------------- launch ----------------
extern "C" void kernel_launch(void* const* d_in, const int* in_sizes, int n_in,
                              void* d_out, int out_size){
    const float* colors = (const float*)d_in[0];
    const int*   align  = (const int*)  d_in[1];
    const float* mus    = (const float*)d_in[2];
    const float* fw1    = (const float*)d_in[3];
    const float* fb1    = (const float*)d_in[4];
    const float* fw2    = (const float*)d_in[5];
    const float* fb2    = (const float*)d_in[6];
    const float* dw1    = (const float*)d_in[7];
    const float* db1    = (const float*)d_in[8];
    const float* dw2    = (const float*)d_in[9];
    const float* db2    = (const float*)d_in[10];

    k_prep<<<1, 512>>>(mus, fw1, fb1, fw2, fb2, dw1, dw2);
    k_chromes<<<(LANG*KK + 255)/256, 256>>>(colors, db1, db2);
    k_buildM<<<NPT, NPT>>>(mus);
    chol_all<<<CB, 256>>>();
    k_pairs2<<<NPAIR/4, 128>>>(align, mus);
    k_final<<<1, 512>>>((float*)d_out);
}

// round 11
// speedup vs baseline: 2.2350x; 1.3930x over previous
#include <cuda_runtime.h>
#include <math.h>

#define NPT   512
#define LANG  500
#define AA    32
#define KK    64
#define NPAIR (LANG*AA)
#define CB    28
#define LOG2PI_F     1.8378770664093453f
#define HALF3LOG2PI  (1.5f*LOG2PI_F)

typedef unsigned long long ull;

// ---------------- device scratch (no allocations allowed) ----------------
__device__ float g_M[NPT*NPT];        // L + I, updated in place by right-looking steps
__device__ float g_diag[NPT];         // pivots d_k of the big factorization
__device__ float g_q[NPT];
__device__ float g_chr[LANG*KK*3];
__device__ float g_pair[NPAIR];       // logdet(sub) + step4 per (lang, a)
__device__ float g_w2inv[9];
__device__ float g_w1inv[9];
__device__ float g_step2;
__device__ int   g_bar;               // persistent-kernel barrier counter

// dynamic smem layout for chol_all (floats):
//  sL   [64][65]   (scaled Cholesky factor of diag block)
//  sA   [64][65]   (TRSM'd row-panel bi)
//  sB   [64][65]   (TRSM'd row-panel bj)
//  sPiv [64], sID [64], scol [2][64]
#define SMEM_CHOL_FLOATS (3*64*65 + 64 + 64 + 128)
#define SMEM_CHOL_BYTES  (SMEM_CHOL_FLOATS*4)

// ---------------- packed f32x2 helpers ----------------
__device__ __forceinline__ ull pack2(float lo, float hi){
    ull r; asm("mov.b64 %0, {%1, %2};" : "=l"(r) : "f"(lo), "f"(hi)); return r;
}
__device__ __forceinline__ void unpack2(ull v, float& lo, float& hi){
    asm("mov.b64 {%0, %1}, %2;" : "=f"(lo), "=f"(hi) : "l"(v));
}
__device__ __forceinline__ void ffma2(ull& d, ull a, ull b){
    asm("fma.rn.f32x2 %0, %1, %2, %0;" : "+l"(d) : "l"(a), "l"(b));
}
__device__ __forceinline__ float frcp(float x){
    float r; asm("rcp.approx.f32 %0, %1;" : "=f"(r) : "f"(x)); return r;
}

// ---------------- helpers ----------------
__device__ __forceinline__ void inv3(const float* w, float* o){
    float a=w[0],b=w[1],c=w[2],d=w[3],e=w[4],f=w[5],g=w[6],h=w[7],i=w[8];
    float det = a*(e*i-f*h) - b*(d*i-f*g) + c*(d*h-e*g);
    float id  = 1.0f/det;
    o[0]=(e*i-f*h)*id; o[1]=(c*h-b*i)*id; o[2]=(b*f-c*e)*id;
    o[3]=(f*g-d*i)*id; o[4]=(a*i-c*g)*id; o[5]=(c*d-a*f)*id;
    o[6]=(d*h-e*g)*id; o[7]=(b*g-a*h)*id; o[8]=(a*e-b*d)*id;
}

// ---------------- K1: q vector, step2, 3x3 inverses ----------------
__global__ void k_prep(const float* __restrict__ mus,
                       const float* __restrict__ fw1, const float* __restrict__ fb1,
                       const float* __restrict__ fw2, const float* __restrict__ fb2,
                       const float* __restrict__ dw1, const float* __restrict__ dw2){
    int t = threadIdx.x;                       // 512 threads
    __shared__ float red[512];
    float contrib = 0.f;
    if (t < NPT){
        float m0=mus[t*3+0], m1=mus[t*3+1], m2=mus[t*3+2];
        float h0 = tanhf(fw1[0]*m0+fw1[1]*m1+fw1[2]*m2+fb1[0]);
        float h1 = tanhf(fw1[3]*m0+fw1[4]*m1+fw1[5]*m2+fb1[1]);
        float h2 = tanhf(fw1[6]*m0+fw1[7]*m1+fw1[8]*m2+fb1[2]);
        float lq = fw2[0]*h0+fw2[1]*h1+fw2[2]*h2+fb2[0];
        g_q[t] = expf(lq);
        contrib = -0.5f*(m0*m0+m1*m1+m2*m2) - HALF3LOG2PI;
    }
    red[t]=contrib; __syncthreads();
    for (int s=256;s>0;s>>=1){ if(t<s) red[t]+=red[t+s]; __syncthreads(); }
    if (t==0){
        g_step2 = red[0];
        inv3(dw1, g_w1inv);
        inv3(dw2, g_w2inv);
    }
}

// ---------------- K2: chromes via inverse flow ----------------
__global__ void k_chromes(const float* __restrict__ colors,
                          const float* __restrict__ db1, const float* __restrict__ db2){
    int idx = blockIdx.x*blockDim.x + threadIdx.x;   // 0 .. 31999
    if (idx >= LANG*KK) return;
    float c0 = colors[idx*3+0]-db2[0];
    float c1 = colors[idx*3+1]-db2[1];
    float c2 = colors[idx*3+2]-db2[2];
    float z0 = g_w2inv[0]*c0 + g_w2inv[1]*c1 + g_w2inv[2]*c2;
    float z1 = g_w2inv[3]*c0 + g_w2inv[4]*c1 + g_w2inv[5]*c2;
    float z2 = g_w2inv[6]*c0 + g_w2inv[7]*c1 + g_w2inv[8]*c2;
    const float lim = 1.0f - 1e-6f;
    z0 = atanhf(fminf(fmaxf(z0,-lim),lim));
    z1 = atanhf(fminf(fmaxf(z1,-lim),lim));
    z2 = atanhf(fminf(fmaxf(z2,-lim),lim));
    float y0 = z0 - db1[0], y1 = z1 - db1[1], y2 = z2 - db1[2];
    g_chr[idx*3+0] = g_w1inv[0]*y0 + g_w1inv[1]*y1 + g_w1inv[2]*y2;
    g_chr[idx*3+1] = g_w1inv[3]*y0 + g_w1inv[4]*y1 + g_w1inv[5]*y2;
    g_chr[idx*3+2] = g_w1inv[6]*y0 + g_w1inv[7]*y1 + g_w1inv[8]*y2;
}

// ---------------- K3: build M = L + I (512 x 512); also reset barrier ----------------
__global__ void k_buildM(const float* __restrict__ mus){
    int i = blockIdx.x, j = threadIdx.x;
    if (i==0 && j==0) g_bar = 0;
    float dx = mus[i*3+0]-mus[j*3+0];
    float dy = mus[i*3+1]-mus[j*3+1];
    float dz = mus[i*3+2]-mus[j*3+2];
    float v = g_q[i]*g_q[j]*__expf(-0.5f*(dx*dx+dy*dy+dz*dz));
    if (i==j) v += 1.0f;
    g_M[i*NPT+j] = v;
}

// ---------------- K4: warp-per-pair 64x64 LDL^T logdet + step4 ----------------
__device__ __forceinline__ float subent(float mx,float my,float mz,float q,
                                        float ox,float oy,float oz,float oq,
                                        int j,int row){
    float dx=mx-ox, dy=my-oy, dz=mz-oz;
    float d2 = dx*dx + dy*dy + dz*dz;
    float v = q*oq*__expf(-0.5f*d2);
    v = (j < row) ? v : 0.f;
    v = (j == row) ? (q*q + 1e-6f) : v;
    return v;
}

__global__ __launch_bounds__(128) void k_pairs2(const int* __restrict__ align,
                                                const float* __restrict__ mus){
    __shared__ float sx[4][64], sy[4][64], sz[4][64], sq[4][64];
    __shared__ __align__(16) float scol[4][2][64];

    int w   = threadIdx.x >> 5;
    int l   = threadIdx.x & 31;
    int pid = blockIdx.x*4 + w;
    int lang = pid >> 5;
    int rrow = 63 - l;

    int base = pid*64;
    int i0 = align[base + l];
    int i1 = align[base + 32 + l];
    float t_x = mus[i0*3+0], t_y = mus[i0*3+1], t_z = mus[i0*3+2];
    float b_x = mus[i1*3+0], b_y = mus[i1*3+1], b_z = mus[i1*3+2];
    float qt  = g_q[i0];
    float q1  = g_q[i1];
    sx[w][l]=t_x;    sy[w][l]=t_y;    sz[w][l]=t_z;    sq[w][l]=qt;
    sx[w][32+l]=b_x; sy[w][32+l]=b_y; sz[w][32+l]=b_z; sq[w][32+l]=q1;

    const float* ch0 = g_chr + (lang*KK + l)*3;
    const float* ch1 = g_chr + (lang*KK + 32 + l)*3;
    float dx0=ch0[0]-t_x, dy0=ch0[1]-t_y, dz0=ch0[2]-t_z;
    float dx1=ch1[0]-b_x, dy1=ch1[1]-b_y, dz1=ch1[2]-b_z;
    float acc = -0.5f*(dx0*dx0+dy0*dy0+dz0*dz0) - HALF3LOG2PI
                -0.5f*(dx1*dx1+dy1*dy1+dz1*dz1) - HALF3LOG2PI;
    __syncwarp();

    float r_x = sx[w][rrow], r_y = sy[w][rrow], r_z = sz[w][rrow], qr = sq[w][rrow];

    ull PT[16];
    ull PR[32];
    #pragma unroll
    for (int j2=0;j2<32;j2++){
        int ja = 2*j2, jb = 2*j2+1;
        float ax=sx[w][ja], ay=sy[w][ja], az=sz[w][ja], aq=sq[w][ja];
        float bx=sx[w][jb], by=sy[w][jb], bz=sz[w][jb], bq=sq[w][jb];
        float eR0 = subent(r_x,r_y,r_z,qr, ax,ay,az,aq, ja, rrow);
        float eR1 = subent(r_x,r_y,r_z,qr, bx,by,bz,bq, jb, rrow);
        PR[j2] = pack2(eR0, eR1);
        if (j2 < 16){
            float eT0 = subent(t_x,t_y,t_z,qt, ax,ay,az,aq, ja, l);
            float eT1 = subent(t_x,t_y,t_z,qt, bx,by,bz,bq, jb, l);
            PT[j2] = pack2(eT0, eT1);
        }
    }

    float pT = 1.f, pR = 1.f;
    #pragma unroll
    for (int k=0;k<64;k++){
        float* sc = &scol[w][k & 1][0];
        float cT = 0.f;
        if (k < 32){
            float lo, hi; unpack2(PT[k>>1], lo, hi);
            cT = (k & 1) ? hi : lo;
        }
        float rlo, rhi; unpack2(PR[k>>1], rlo, rhi);
        float cR = (k & 1) ? rhi : rlo;
        if (k < 32 && l >= k) sc[l] = cT;
        if (rrow >= k)        sc[rrow] = cR;
        __syncwarp();
        float piv = fmaxf(sc[k], 1e-7f);
        pT = (k == l)    ? piv : pT;
        pR = (k == rrow) ? piv : pR;
        float rv = frcp(piv);
        float fT = cT*rv, fR = cR*rv;
        ull nT = pack2(-fT, -fT);
        ull nR = pack2(-fR, -fR);
        const ull* cp = (const ull*)sc;
        #pragma unroll
        for (int j2=0;j2<32;j2++){
            if (j2 >= ((k+1)>>1)){
                ull c = cp[j2];
                if (j2 < 16) ffma2(PT[j2], nT, c);
                ffma2(PR[j2], nR, c);
            }
        }
    }
    acc += logf(pT) + logf(pR);

    #pragma unroll
    for (int o=16;o>0;o>>=1) acc += __shfl_down_sync(0xffffffffu, acc, o);
    if (l == 0) g_pair[pid] = acc;
}

// ---------------- K5: persistent 512x512 Cholesky, warp-level panels ----------------
__device__ __forceinline__ void gbar(int tgt){
    __syncthreads();
    if (threadIdx.x == 0){
        __threadfence();
        atomicAdd(&g_bar, 1);
        while (*((volatile int*)&g_bar) < tgt*CB) { __nanosleep(32); }
        __threadfence();
    }
    __syncthreads();
}

// warp-level LDL^T of the 64x64 diag block at (p,p) of g_M (read via __ldcg).
// Lane l owns rows l (PT) and 63-l (PR). Writes sPiv, sID, and the scaled
// Cholesky factor sL PROGRESSIVELY: at step k, cT/cR hold a_row[k] after
// updates 0..k-1 (the true eliminated value), so sL[row][k] = c * rsqrt(piv)
// is captured BEFORE the pair-granular update clobbers even-index columns.
__device__ __forceinline__ void diag_ldl_warp(int p, int l,
                                              float* scol, float* sPiv, float* sID,
                                              float (*sL)[65]){
    int rrow = 63 - l;
    const float2* r0 = (const float2*)(g_M + (p*64 + l)*NPT + p*64);
    const float2* r1 = (const float2*)(g_M + (p*64 + rrow)*NPT + p*64);
    ull PT[16];
    ull PR[32];
    #pragma unroll
    for (int j2=0;j2<32;j2++){
        float2 v1 = __ldcg(r1 + j2);
        PR[j2] = pack2(v1.x, v1.y);
        if (j2 < 16){
            float2 v0 = __ldcg(r0 + j2);
            PT[j2] = pack2(v0.x, v0.y);
        }
    }
    #pragma unroll
    for (int k=0;k<64;k++){
        float* sc = scol + (k&1)*64;
        float cT = 0.f;
        if (k < 32){
            float lo, hi; unpack2(PT[k>>1], lo, hi);
            cT = (k & 1) ? hi : lo;
        }
        float rlo, rhi; unpack2(PR[k>>1], rlo, rhi);
        float cR = (k & 1) ? rhi : rlo;
        if (k < 32 && l >= k) sc[l] = cT;
        if (rrow >= k)        sc[rrow] = cR;
        __syncwarp();
        float piv = fmaxf(sc[k], 1e-30f);
        if (l == (k & 31)) sPiv[k] = piv;
        float rs = rsqrtf(piv);
        if (k < 32 && l >= k) sL[l][k]    = cT*rs;   // progressive L capture
        if (rrow >= k)        sL[rrow][k] = cR*rs;
        float rv = frcp(piv);
        float fT = cT*rv, fR = cR*rv;
        ull nT = pack2(-fT, -fT);
        ull nR = pack2(-fR, -fR);
        const ull* cp = (const ull*)sc;
        #pragma unroll
        for (int j2=0;j2<32;j2++){
            if (j2 >= ((k+1)>>1)){
                ull c = cp[j2];
                if (j2 < 16) ffma2(PT[j2], nT, c);
                ffma2(PR[j2], nR, c);
            }
        }
    }
    __syncwarp();
    sID[l]    = rsqrtf(sPiv[l]);
    sID[32+l] = rsqrtf(sPiv[32+l]);
    __syncwarp();
}

__global__ __launch_bounds__(256) void chol_all(){
    extern __shared__ float dsm[];
    float (*sL)[65] = (float(*)[65])dsm;
    float (*sA)[65] = (float(*)[65])(dsm + 64*65);
    float (*sB)[65] = (float(*)[65])(dsm + 2*64*65);
    float* sPiv = dsm + 3*64*65;
    float* sID  = sPiv + 64;
    float* scol = sID + 64;

    int b = blockIdx.x, t = threadIdx.x;
    int w = t >> 5, l = t & 31;

    #pragma unroll 1
    for (int p=0; p<8; p++){
        int m = 7 - p;
        int ntile = m*(m+1)/2;
        bool active = (b < ntile);
        int bi=0, bj=0; bool same=false;
        if (active){
            int br = 0;
            while ((br+1)*(br+2)/2 <= b) br++;
            int bc = b - br*(br+1)/2;
            bi = p+1+br; bj = p+1+bc;
            same = (bi == bj);
        }
        bool dodiag = active || (b == 0);

        // phase 1: warp 0 factors diag block; warps 4-7 load their TRSM rows
        int tt  = t - 128;
        int sel = tt >> 6, r = tt & 63;
        bool dotrsm = (t >= 128) && active && !(same && sel == 1);
        float v[64];
        if (dotrsm){
            const float2* src = (const float2*)(g_M + ((sel ? bj : bi)*64 + r)*NPT + p*64);
            #pragma unroll
            for (int u=0; u<32; u++){
                float2 x = __ldcg(src + u);
                v[2*u] = x.x; v[2*u+1] = x.y;
            }
        }
        if (w == 0 && dodiag){
            diag_ldl_warp(p, l, scol, sPiv, sID, sL);
            if (b == 0){
                g_diag[p*64 + l]      = sPiv[l];
                g_diag[p*64 + 32 + l] = sPiv[32 + l];
            }
        }
        __syncthreads();

        if (p == 7) break;                       // pivots-only tail, no barrier

        // phase 2: TRSM (rows solved in registers against shared L11)
        if (dotrsm){
            #pragma unroll
            for (int j=0;j<64;j++){
                float s0=0.f,s1=0.f,s2=0.f,s3=0.f;
                int q=0;
                #pragma unroll
                for (; q+3<j; q+=4){
                    s0 += v[q+0]*sL[j][q+0];
                    s1 += v[q+1]*sL[j][q+1];
                    s2 += v[q+2]*sL[j][q+2];
                    s3 += v[q+3]*sL[j][q+3];
                }
                #pragma unroll
                for (; q<j; q++) s0 += v[q]*sL[j][q];
                v[j] = (v[j] - ((s0+s1)+(s2+s3))) * sID[j];
            }
            float (*P)[65] = sel ? sB : sA;
            #pragma unroll
            for (int j=0;j<64;j++) P[r][j] = v[j];
        }
        __syncthreads();

        // phase 3: SYRK  C(bi,bj) -= Anew * Bnew^T   (float4 RMW on gmem)
        if (active){
            float (*PB)[65] = same ? sA : sB;
            int ty = t>>4, tx = t&15, i0 = ty*4, j0 = tx*4;
            float acc[4][4];
            #pragma unroll
            for (int ii=0;ii<4;ii++)
                #pragma unroll
                for (int jj=0;jj<4;jj++) acc[ii][jj]=0.f;
            #pragma unroll
            for (int k=0;k<64;k++){
                float av[4], bv[4];
                #pragma unroll
                for (int ii=0;ii<4;ii++) av[ii]=sA[i0+ii][k];
                #pragma unroll
                for (int jj=0;jj<4;jj++) bv[jj]=PB[j0+jj][k];
                #pragma unroll
                for (int ii=0;ii<4;ii++)
                    #pragma unroll
                    for (int jj=0;jj<4;jj++) acc[ii][jj] += av[ii]*bv[jj];
            }
            float* Cb = g_M + (bi*64)*NPT + bj*64;
            #pragma unroll
            for (int ii=0;ii<4;ii++){
                float4* cp = (float4*)(Cb + (i0+ii)*NPT + j0);
                float4 c = __ldcg(cp);
                c.x -= acc[ii][0]; c.y -= acc[ii][1];
                c.z -= acc[ii][2]; c.w -= acc[ii][3];
                *cp = c;
            }
        }
        gbar(p+1);
    }
}

// ---------------- K6: logsumexp + final assembly ----------------
__global__ void k_final(float* __restrict__ out){
    int t = threadIdx.x;                        // 512 threads
    __shared__ float red[512];
    __shared__ float s_sumlse;
    float lse = 0.f;
    if (t < LANG){
        const float* v = g_pair + t*AA;
        float mx = -3.4e38f;
        #pragma unroll
        for (int a=0;a<AA;a++) mx = fmaxf(mx, v[a]);
        float s = 0.f;
        #pragma unroll
        for (int a=0;a<AA;a++) s += expf(v[a]-mx);
        lse = mx + logf(s);
    }
    red[t]=lse; __syncthreads();
    for (int s=256;s>0;s>>=1){ if(t<s) red[t]+=red[t+s]; __syncthreads(); }
    if (t==0) s_sumlse = red[0];
    __syncthreads();
    float ld = logf(g_diag[t]);
    red[t]=ld; __syncthreads();
    for (int s=256;s>0;s>>=1){ if(t<s) red[t]+=red[t+s]; __syncthreads(); }
    if (t==0){
        float logdetLI = red[0];
        float step1 = 512.f*logf(500.f) - 500.f - lgammaf(513.f);
        out[0] = -(step1 + g_step2 + s_sumlse - (float)LANG*logdetLI);
    }
}

// ---------------- launch ----------------
extern "C" void kernel_launch(void* const* d_in, const int* in_sizes, int n_in,
                              void* d_out, int out_size){
    const float* colors = (const float*)d_in[0];
    const int*   align  = (const int*)  d_in[1];
    const float* mus    = (const float*)d_in[2];
    const float* fw1    = (const float*)d_in[3];
    const float* fb1    = (const float*)d_in[4];
    const float* fw2    = (const float*)d_in[5];
    const float* fb2    = (const float*)d_in[6];
    const float* dw1    = (const float*)d_in[7];
    const float* db1    = (const float*)d_in[8];
    const float* dw2    = (const float*)d_in[9];
    const float* db2    = (const float*)d_in[10];

    cudaFuncSetAttribute(chol_all, cudaFuncAttributeMaxDynamicSharedMemorySize,
                         SMEM_CHOL_BYTES);

    k_prep<<<1, 512>>>(mus, fw1, fb1, fw2, fb2, dw1, dw2);
    k_chromes<<<(LANG*KK + 255)/256, 256>>>(colors, db1, db2);
    k_buildM<<<NPT, NPT>>>(mus);
    chol_all<<<CB, 256, SMEM_CHOL_BYTES>>>();
    k_pairs2<<<NPAIR/4, 128>>>(align, mus);
    k_final<<<1, 512>>>((float*)d_out);
}

// round 14
// speedup vs baseline: 3.3115x; 1.4817x over previous
#include <cuda_runtime.h>
#include <math.h>

#define NPT   512
#define LANG  500
#define AA    32
#define KK    64
#define NPAIR (LANG*AA)
#define CB    28
#define PAIRS_PER_BLK 8
#define PBLKS (NPAIR/PAIRS_PER_BLK)
#define LOG2PI_F     1.8378770664093453f
#define HALF3LOG2PI  (1.5f*LOG2PI_F)

typedef unsigned long long ull;

// ---------------- device scratch (no allocations allowed) ----------------
__device__ float g_M[NPT*NPT];        // L + I, updated in place by right-looking steps
__device__ float g_diag[NPT];         // pivots d_k of the big factorization
__device__ float g_q[NPT];
__device__ float g_chr[LANG*KK*3];
__device__ float g_pair[NPAIR];       // logdet(sub) + step4 per (lang, a)
__device__ float g_w2inv[9];
__device__ float g_w1inv[9];
__device__ float g_step2;
__device__ int   g_bar;               // persistent-kernel barrier counter

// dynamic smem layout for the fused kernel (floats), chol path:
//  sL   [64][65]   (scaled Cholesky factor of diag block)
//  sA   [64][65]   (TRSM'd row-panel bi)
//  sB   [64][65]   (TRSM'd row-panel bj)
//  sPiv [64], sID [64], scol [2][64]
// pairs path: 8 warps x 384 floats (sx,sy,sz,sq[64] each + scol[2][64]) = 3072 floats
#define SMEM_CHOL_FLOATS (3*64*65 + 64 + 64 + 128)
#define SMEM_CHOL_BYTES  (SMEM_CHOL_FLOATS*4)

// ---------------- packed f32x2 helpers ----------------
__device__ __forceinline__ ull pack2(float lo, float hi){
    ull r; asm("mov.b64 %0, {%1, %2};" : "=l"(r) : "f"(lo), "f"(hi)); return r;
}
__device__ __forceinline__ void unpack2(ull v, float& lo, float& hi){
    asm("mov.b64 {%0, %1}, %2;" : "=f"(lo), "=f"(hi) : "l"(v));
}
__device__ __forceinline__ void ffma2(ull& d, ull a, ull b){
    asm("fma.rn.f32x2 %0, %1, %2, %0;" : "+l"(d) : "l"(a), "l"(b));
}
__device__ __forceinline__ float frcp(float x){
    float r; asm("rcp.approx.f32 %0, %1;" : "=f"(r) : "f"(x)); return r;
}

// ---------------- helpers ----------------
__device__ __forceinline__ void inv3(const float* w, float* o){
    float a=w[0],b=w[1],c=w[2],d=w[3],e=w[4],f=w[5],g=w[6],h=w[7],i=w[8];
    float det = a*(e*i-f*h) - b*(d*i-f*g) + c*(d*h-e*g);
    float id  = 1.0f/det;
    o[0]=(e*i-f*h)*id; o[1]=(c*h-b*i)*id; o[2]=(b*f-c*e)*id;
    o[3]=(f*g-d*i)*id; o[4]=(a*i-c*g)*id; o[5]=(c*d-a*f)*id;
    o[6]=(d*h-e*g)*id; o[7]=(b*g-a*h)*id; o[8]=(a*e-b*d)*id;
}

// ---------------- K1: q vector, step2, 3x3 inverses ----------------
__global__ void k_prep(const float* __restrict__ mus,
                       const float* __restrict__ fw1, const float* __restrict__ fb1,
                       const float* __restrict__ fw2, const float* __restrict__ fb2,
                       const float* __restrict__ dw1, const float* __restrict__ dw2){
    int t = threadIdx.x;                       // 512 threads
    __shared__ float red[512];
    float contrib = 0.f;
    if (t < NPT){
        float m0=mus[t*3+0], m1=mus[t*3+1], m2=mus[t*3+2];
        float h0 = tanhf(fw1[0]*m0+fw1[1]*m1+fw1[2]*m2+fb1[0]);
        float h1 = tanhf(fw1[3]*m0+fw1[4]*m1+fw1[5]*m2+fb1[1]);
        float h2 = tanhf(fw1[6]*m0+fw1[7]*m1+fw1[8]*m2+fb1[2]);
        float lq = fw2[0]*h0+fw2[1]*h1+fw2[2]*h2+fb2[0];
        g_q[t] = expf(lq);
        contrib = -0.5f*(m0*m0+m1*m1+m2*m2) - HALF3LOG2PI;
    }
    red[t]=contrib; __syncthreads();
    for (int s=256;s>0;s>>=1){ if(t<s) red[t]+=red[t+s]; __syncthreads(); }
    if (t==0){
        g_step2 = red[0];
        inv3(dw1, g_w1inv);
        inv3(dw2, g_w2inv);
    }
}

// ---------------- K2: chromes via inverse flow ----------------
__global__ void k_chromes(const float* __restrict__ colors,
                          const float* __restrict__ db1, const float* __restrict__ db2){
    int idx = blockIdx.x*blockDim.x + threadIdx.x;   // 0 .. 31999
    if (idx >= LANG*KK) return;
    float c0 = colors[idx*3+0]-db2[0];
    float c1 = colors[idx*3+1]-db2[1];
    float c2 = colors[idx*3+2]-db2[2];
    float z0 = g_w2inv[0]*c0 + g_w2inv[1]*c1 + g_w2inv[2]*c2;
    float z1 = g_w2inv[3]*c0 + g_w2inv[4]*c1 + g_w2inv[5]*c2;
    float z2 = g_w2inv[6]*c0 + g_w2inv[7]*c1 + g_w2inv[8]*c2;
    const float lim = 1.0f - 1e-6f;
    z0 = atanhf(fminf(fmaxf(z0,-lim),lim));
    z1 = atanhf(fminf(fmaxf(z1,-lim),lim));
    z2 = atanhf(fminf(fmaxf(z2,-lim),lim));
    float y0 = z0 - db1[0], y1 = z1 - db1[1], y2 = z2 - db1[2];
    g_chr[idx*3+0] = g_w1inv[0]*y0 + g_w1inv[1]*y1 + g_w1inv[2]*y2;
    g_chr[idx*3+1] = g_w1inv[3]*y0 + g_w1inv[4]*y1 + g_w1inv[5]*y2;
    g_chr[idx*3+2] = g_w1inv[6]*y0 + g_w1inv[7]*y1 + g_w1inv[8]*y2;
}

// ---------------- K3: build M = L + I (512 x 512); also reset barrier ----------------
__global__ void k_buildM(const float* __restrict__ mus){
    int i = blockIdx.x, j = threadIdx.x;
    if (i==0 && j==0) g_bar = 0;
    float dx = mus[i*3+0]-mus[j*3+0];
    float dy = mus[i*3+1]-mus[j*3+1];
    float dz = mus[i*3+2]-mus[j*3+2];
    float v = g_q[i]*g_q[j]*__expf(-0.5f*(dx*dx+dy*dy+dz*dz));
    if (i==j) v += 1.0f;
    g_M[i*NPT+j] = v;
}

// ---------------- pairs path: warp-per-pair 64x64 LDL^T logdet + step4 ----------------
__device__ __forceinline__ float subent(float mx,float my,float mz,float q,
                                        float ox,float oy,float oz,float oq,
                                        int j,int row){
    float dx=mx-ox, dy=my-oy, dz=mz-oz;
    float d2 = dx*dx + dy*dy + dz*dz;
    float v = q*oq*__expf(-0.5f*d2);
    v = (j < row) ? v : 0.f;
    v = (j == row) ? (q*q + 1e-6f) : v;
    return v;
}

// ws: per-warp shared slice of 384 floats: sx[64],sy[64],sz[64],sq[64],scol[2][64]
__device__ void pairs_warp(float* ws, int pid, int l,
                           const int* __restrict__ align,
                           const float* __restrict__ mus){
    float* sx = ws;
    float* sy = ws + 64;
    float* sz = ws + 128;
    float* sq = ws + 192;
    float* scol = ws + 256;

    int lang = pid >> 5;
    int rrow = 63 - l;

    int base = pid*64;
    int i0 = align[base + l];
    int i1 = align[base + 32 + l];
    float t_x = mus[i0*3+0], t_y = mus[i0*3+1], t_z = mus[i0*3+2];
    float b_x = mus[i1*3+0], b_y = mus[i1*3+1], b_z = mus[i1*3+2];
    float qt  = g_q[i0];
    float q1  = g_q[i1];
    sx[l]=t_x;    sy[l]=t_y;    sz[l]=t_z;    sq[l]=qt;
    sx[32+l]=b_x; sy[32+l]=b_y; sz[32+l]=b_z; sq[32+l]=q1;

    const float* ch0 = g_chr + (lang*KK + l)*3;
    const float* ch1 = g_chr + (lang*KK + 32 + l)*3;
    float dx0=ch0[0]-t_x, dy0=ch0[1]-t_y, dz0=ch0[2]-t_z;
    float dx1=ch1[0]-b_x, dy1=ch1[1]-b_y, dz1=ch1[2]-b_z;
    float acc = -0.5f*(dx0*dx0+dy0*dy0+dz0*dz0) - HALF3LOG2PI
                -0.5f*(dx1*dx1+dy1*dy1+dz1*dz1) - HALF3LOG2PI;
    __syncwarp();

    float r_x = sx[rrow], r_y = sy[rrow], r_z = sz[rrow], qr = sq[rrow];

    ull PT[16];
    ull PR[32];
    #pragma unroll
    for (int j2=0;j2<32;j2++){
        int ja = 2*j2, jb = 2*j2+1;
        float ax=sx[ja], ay=sy[ja], az=sz[ja], aq=sq[ja];
        float bx=sx[jb], by=sy[jb], bz=sz[jb], bq=sq[jb];
        float eR0 = subent(r_x,r_y,r_z,qr, ax,ay,az,aq, ja, rrow);
        float eR1 = subent(r_x,r_y,r_z,qr, bx,by,bz,bq, jb, rrow);
        PR[j2] = pack2(eR0, eR1);
        if (j2 < 16){
            float eT0 = subent(t_x,t_y,t_z,qt, ax,ay,az,aq, ja, l);
            float eT1 = subent(t_x,t_y,t_z,qt, bx,by,bz,bq, jb, l);
            PT[j2] = pack2(eT0, eT1);
        }
    }

    float pT = 1.f, pR = 1.f;
    #pragma unroll
    for (int k=0;k<64;k++){
        float* sc = scol + (k & 1)*64;
        float cT = 0.f;
        if (k < 32){
            float lo, hi; unpack2(PT[k>>1], lo, hi);
            cT = (k & 1) ? hi : lo;
        }
        float rlo, rhi; unpack2(PR[k>>1], rlo, rhi);
        float cR = (k & 1) ? rhi : rlo;
        if (k < 32 && l >= k) sc[l] = cT;
        if (rrow >= k)        sc[rrow] = cR;
        __syncwarp();
        float piv = fmaxf(sc[k], 1e-7f);
        pT = (k == l)    ? piv : pT;
        pR = (k == rrow) ? piv : pR;
        float rv = frcp(piv);
        float fT = cT*rv, fR = cR*rv;
        ull nT = pack2(-fT, -fT);
        ull nR = pack2(-fR, -fR);
        const ull* cp = (const ull*)sc;
        #pragma unroll
        for (int j2=0;j2<32;j2++){
            if (j2 >= ((k+1)>>1)){
                ull c = cp[j2];
                if (j2 < 16) ffma2(PT[j2], nT, c);
                ffma2(PR[j2], nR, c);
            }
        }
    }
    acc += logf(pT) + logf(pR);

    #pragma unroll
    for (int o=16;o>0;o>>=1) acc += __shfl_down_sync(0xffffffffu, acc, o);
    if (l == 0) g_pair[pid] = acc;
}

// ---------------- chol path: persistent 512x512 Cholesky, warp-level panels ----------------
__device__ __forceinline__ void gbar(int tgt){
    __syncthreads();
    if (threadIdx.x == 0){
        __threadfence();
        atomicAdd(&g_bar, 1);
        while (*((volatile int*)&g_bar) < tgt*CB) { __nanosleep(32); }
        __threadfence();
    }
    __syncthreads();
}

// warp-level LDL^T of the 64x64 diag block at (p,p) of g_M (read via __ldcg).
// Lane l owns rows l (PT) and 63-l (PR). Writes sPiv, sID, and the scaled
// Cholesky factor sL PROGRESSIVELY: at step k, cT/cR hold a_row[k] after
// updates 0..k-1 (the true eliminated value), so sL[row][k] = c * rsqrt(piv)
// is captured BEFORE the pair-granular update clobbers even-index columns.
__device__ __forceinline__ void diag_ldl_warp(int p, int l,
                                              float* scol, float* sPiv, float* sID,
                                              float (*sL)[65]){
    int rrow = 63 - l;
    const float2* r0 = (const float2*)(g_M + (p*64 + l)*NPT + p*64);
    const float2* r1 = (const float2*)(g_M + (p*64 + rrow)*NPT + p*64);
    ull PT[16];
    ull PR[32];
    #pragma unroll
    for (int j2=0;j2<32;j2++){
        float2 v1 = __ldcg(r1 + j2);
        PR[j2] = pack2(v1.x, v1.y);
        if (j2 < 16){
            float2 v0 = __ldcg(r0 + j2);
            PT[j2] = pack2(v0.x, v0.y);
        }
    }
    #pragma unroll
    for (int k=0;k<64;k++){
        float* sc = scol + (k&1)*64;
        float cT = 0.f;
        if (k < 32){
            float lo, hi; unpack2(PT[k>>1], lo, hi);
            cT = (k & 1) ? hi : lo;
        }
        float rlo, rhi; unpack2(PR[k>>1], rlo, rhi);
        float cR = (k & 1) ? rhi : rlo;
        if (k < 32 && l >= k) sc[l] = cT;
        if (rrow >= k)        sc[rrow] = cR;
        __syncwarp();
        float piv = fmaxf(sc[k], 1e-30f);
        if (l == (k & 31)) sPiv[k] = piv;
        float rs = rsqrtf(piv);
        if (k < 32 && l >= k) sL[l][k]    = cT*rs;   // progressive L capture
        if (rrow >= k)        sL[rrow][k] = cR*rs;
        float rv = frcp(piv);
        float fT = cT*rv, fR = cR*rv;
        ull nT = pack2(-fT, -fT);
        ull nR = pack2(-fR, -fR);
        const ull* cp = (const ull*)sc;
        #pragma unroll
        for (int j2=0;j2<32;j2++){
            if (j2 >= ((k+1)>>1)){
                ull c = cp[j2];
                if (j2 < 16) ffma2(PT[j2], nT, c);
                ffma2(PR[j2], nR, c);
            }
        }
    }
    __syncwarp();
    sID[l]    = rsqrtf(sPiv[l]);
    sID[32+l] = rsqrtf(sPiv[32+l]);
    __syncwarp();
}

__device__ void chol_block(float* dsm){
    float (*sL)[65] = (float(*)[65])dsm;
    float (*sA)[65] = (float(*)[65])(dsm + 64*65);
    float (*sB)[65] = (float(*)[65])(dsm + 2*64*65);
    float* sPiv = dsm + 3*64*65;
    float* sID  = sPiv + 64;
    float* scol = sID + 64;

    int b = blockIdx.x, t = threadIdx.x;
    int w = t >> 5, l = t & 31;

    #pragma unroll 1
    for (int p=0; p<8; p++){
        int m = 7 - p;
        int ntile = m*(m+1)/2;
        bool active = (b < ntile);
        int bi=0, bj=0; bool same=false;
        if (active){
            int br = 0;
            while ((br+1)*(br+2)/2 <= b) br++;
            int bc = b - br*(br+1)/2;
            bi = p+1+br; bj = p+1+bc;
            same = (bi == bj);
        }
        bool dodiag = active || (b == 0);

        // phase 1: warp 0 factors diag block; warps 4-7 load their TRSM rows
        int tt  = t - 128;
        int sel = tt >> 6, r = tt & 63;
        bool dotrsm = (t >= 128) && active && !(same && sel == 1);
        float v[64];
        if (dotrsm){
            const float2* src = (const float2*)(g_M + ((sel ? bj : bi)*64 + r)*NPT + p*64);
            #pragma unroll
            for (int u=0; u<32; u++){
                float2 x = __ldcg(src + u);
                v[2*u] = x.x; v[2*u+1] = x.y;
            }
        }
        if (w == 0 && dodiag){
            diag_ldl_warp(p, l, scol, sPiv, sID, sL);
            if (b == 0){
                g_diag[p*64 + l]      = sPiv[l];
                g_diag[p*64 + 32 + l] = sPiv[32 + l];
            }
        }
        __syncthreads();

        if (p == 7) break;                       // pivots-only tail, no barrier

        // phase 2: TRSM (rows solved in registers against shared L11)
        if (dotrsm){
            #pragma unroll
            for (int j=0;j<64;j++){
                float s0=0.f,s1=0.f,s2=0.f,s3=0.f;
                int q=0;
                #pragma unroll
                for (; q+3<j; q+=4){
                    s0 += v[q+0]*sL[j][q+0];
                    s1 += v[q+1]*sL[j][q+1];
                    s2 += v[q+2]*sL[j][q+2];
                    s3 += v[q+3]*sL[j][q+3];
                }
                #pragma unroll
                for (; q<j; q++) s0 += v[q]*sL[j][q];
                v[j] = (v[j] - ((s0+s1)+(s2+s3))) * sID[j];
            }
            float (*P)[65] = sel ? sB : sA;
            #pragma unroll
            for (int j=0;j<64;j++) P[r][j] = v[j];
        }
        __syncthreads();

        // phase 3: SYRK  C(bi,bj) -= Anew * Bnew^T   (float4 RMW on gmem)
        if (active){
            float (*PB)[65] = same ? sA : sB;
            int ty = t>>4, tx = t&15, i0 = ty*4, j0 = tx*4;
            float acc[4][4];
            #pragma unroll
            for (int ii=0;ii<4;ii++)
                #pragma unroll
                for (int jj=0;jj<4;jj++) acc[ii][jj]=0.f;
            #pragma unroll
            for (int k=0;k<64;k++){
                float av[4], bv[4];
                #pragma unroll
                for (int ii=0;ii<4;ii++) av[ii]=sA[i0+ii][k];
                #pragma unroll
                for (int jj=0;jj<4;jj++) bv[jj]=PB[j0+jj][k];
                #pragma unroll
                for (int ii=0;ii<4;ii++)
                    #pragma unroll
                    for (int jj=0;jj<4;jj++) acc[ii][jj] += av[ii]*bv[jj];
            }
            float* Cb = g_M + (bi*64)*NPT + bj*64;
            #pragma unroll
            for (int ii=0;ii<4;ii++){
                float4* cp = (float4*)(Cb + (i0+ii)*NPT + j0);
                float4 c = __ldcg(cp);
                c.x -= acc[ii][0]; c.y -= acc[ii][1];
                c.z -= acc[ii][2]; c.w -= acc[ii][3];
                *cp = c;
            }
        }
        gbar(p+1);
    }
}

// ---------------- fused kernel: blocks 0..27 chol, blocks 28.. pairs ----------------
__global__ __launch_bounds__(256) void k_fused(const int* __restrict__ align,
                                               const float* __restrict__ mus){
    extern __shared__ float dsm[];
    if (blockIdx.x < CB){
        chol_block(dsm);
    } else {
        int w = threadIdx.x >> 5;
        int l = threadIdx.x & 31;
        int pid = (blockIdx.x - CB)*PAIRS_PER_BLK + w;
        pairs_warp(dsm + w*384, pid, l, align, mus);
    }
}

// ---------------- K6: logsumexp + final assembly ----------------
__global__ void k_final(float* __restrict__ out){
    int t = threadIdx.x;                        // 512 threads
    __shared__ float red[512];
    __shared__ float s_sumlse;
    float lse = 0.f;
    if (t < LANG){
        const float* v = g_pair + t*AA;
        float mx = -3.4e38f;
        #pragma unroll
        for (int a=0;a<AA;a++) mx = fmaxf(mx, v[a]);
        float s = 0.f;
        #pragma unroll
        for (int a=0;a<AA;a++) s += expf(v[a]-mx);
        lse = mx + logf(s);
    }
    red[t]=lse; __syncthreads();
    for (int s=256;s>0;s>>=1){ if(t<s) red[t]+=red[t+s]; __syncthreads(); }
    if (t==0) s_sumlse = red[0];
    __syncthreads();
    float ld = logf(g_diag[t]);
    red[t]=ld; __syncthreads();
    for (int s=256;s>0;s>>=1){ if(t<s) red[t]+=red[t+s]; __syncthreads(); }
    if (t==0){
        float logdetLI = red[0];
        float step1 = 512.f*logf(500.f) - 500.f - lgammaf(513.f);
        out[0] = -(step1 + g_step2 + s_sumlse - (float)LANG*logdetLI);
    }
}

// ---------------- launch ----------------
extern "C" void kernel_launch(void* const* d_in, const int* in_sizes, int n_in,
                              void* d_out, int out_size){
    const float* colors = (const float*)d_in[0];
    const int*   align  = (const int*)  d_in[1];
    const float* mus    = (const float*)d_in[2];
    const float* fw1    = (const float*)d_in[3];
    const float* fb1    = (const float*)d_in[4];
    const float* fw2    = (const float*)d_in[5];
    const float* fb2    = (const float*)d_in[6];
    const float* dw1    = (const float*)d_in[7];
    const float* db1    = (const float*)d_in[8];
    const float* dw2    = (const float*)d_in[9];
    const float* db2    = (const float*)d_in[10];

    cudaFuncSetAttribute(k_fused, cudaFuncAttributeMaxDynamicSharedMemorySize,
                         SMEM_CHOL_BYTES);

    k_prep<<<1, 512>>>(mus, fw1, fb1, fw2, fb2, dw1, dw2);
    k_chromes<<<(LANG*KK + 255)/256, 256>>>(colors, db1, db2);
    k_buildM<<<NPT, NPT>>>(mus);
    k_fused<<<CB + PBLKS, 256, SMEM_CHOL_BYTES>>>(align, mus);
    k_final<<<1, 512>>>((float*)d_out);
}